// round 3
// baseline (speedup 1.0000x reference)
#include <cuda_runtime.h>

#define BN   16
#define CN   80
#define HN   128
#define WN   128
#define HWN  (HN*WN)
#define NPLANES (BN*CN)
#define TOPK 100
#define NB1  2048
#define BCAP (1<<18)       // per-batch candidate cap (expected ~145k)
#define SCAP 2048          // per-batch survivor cap (expected ~640)
#define CHUNK 32           // rows per nms block

// ---- scratch (device globals; allocation-free contract) ----
__device__ unsigned long long g_cand[BN][BCAP];   // packed (valbits<<32)|~idx
__device__ unsigned long long g_surv[BN][SCAP];
// zeroed each call via one memset: [BN*NB1 hist | BN ccnt | BN scnt]
__device__ int g_zeroed[BN*NB1 + 2*BN];
#define HIST(b,i) g_zeroed[(b)*NB1 + (i)]
#define CCNT(b)   g_zeroed[BN*NB1 + (b)]
#define SCNT(b)   g_zeroed[BN*NB1 + BN + (b)]

__device__ __forceinline__ int bin1f(float v){
    int b = (int)(v * 2048.0f);
    return b < 0 ? 0 : (b > NB1-1 ? NB1-1 : b);
}

// K1: 3x3 NMS. One block per 32-row chunk of a plane (4 chunks/plane, 5120 blocks).
// Emits packed candidates into per-batch array + scatters per-batch value histogram.
__global__ __launch_bounds__(256) void nms_kernel(const float* __restrict__ hm){
    __shared__ float sp[(CHUNK+2)*WN];     // rows r0-1 .. r0+32
    const int blk   = blockIdx.x;
    const int plane = blk >> 2;
    const int chunk = blk & 3;
    const int b  = plane / CN;
    const int ch = plane % CN;
    const int r0 = chunk * CHUNK;
    const float* base = hm + (size_t)plane * HWN;

    // load 34 rows (guarded at image edges), vectorized float4
    for (int i = threadIdx.x; i < (CHUNK+2)*(WN/4); i += 256){
        int row = i >> 5;                 // /(WN/4)
        int q   = i & 31;
        int g   = r0 - 1 + row;
        if (g >= 0 && g < HN)
            ((float4*)sp)[row*(WN/4) + q] = ((const float4*)(base + (size_t)g*WN))[q];
    }
    __syncthreads();

    const int lane = threadIdx.x & 31;
    const unsigned lmask = (1u << lane) - 1u;
    unsigned long long* dst = g_cand[b];

    #pragma unroll 1
    for (int it = 0; it < (CHUNK*WN)/256; ++it){
        int pix = it*256 + threadIdx.x;
        int row = pix >> 7;               // 0..31
        int x   = pix & (WN-1);
        int y   = r0 + row;
        const float* cur = sp + (row+1)*WN;
        float v = cur[x];
        bool keep = true;
        bool hasL = x > 0, hasR = x < WN-1, hasU = y > 0, hasD = y < HN-1;
        if (hasU){
            const float* r = cur - WN;
            if (hasL && v < r[x-1]) keep = false;
            if (v < r[x])           keep = false;
            if (hasR && v < r[x+1]) keep = false;
        }
        if (hasL && v < cur[x-1]) keep = false;
        if (hasR && v < cur[x+1]) keep = false;
        if (hasD){
            const float* r = cur + WN;
            if (hasL && v < r[x-1]) keep = false;
            if (v < r[x])           keep = false;
            if (hasR && v < r[x+1]) keep = false;
        }

        if (keep) atomicAdd(&HIST(b, bin1f(v)), 1);

        unsigned bal = __ballot_sync(0xffffffffu, keep);
        int wb = 0;
        if (lane == 0 && bal) wb = atomicAdd(&CCNT(b), __popc(bal));
        wb = __shfl_sync(0xffffffffu, wb, 0);
        if (keep){
            int pos = wb + __popc(bal & lmask);
            if (pos < BCAP){
                unsigned vb  = __float_as_uint(v);
                unsigned idx = (unsigned)(ch*HWN + y*WN + x);
                dst[pos] = ((unsigned long long)vb << 32) | (unsigned)(~idx);
            }
        }
    }
}

// K2: per-batch threshold (inline suffix scan of histogram) + compaction.
// grid = (8 slices, BN batches), 256 threads.
__global__ __launch_bounds__(256) void filter_kernel(){
    __shared__ int s0[NB1], s1[NB1];
    __shared__ int sB1;
    const int b   = blockIdx.y;
    const int tid = threadIdx.x;

    for (int i = tid; i < NB1; i += 256) s0[i] = HIST(b, i);
    __syncthreads();
    int* A = s0; int* B = s1;
    for (int off = 1; off < NB1; off <<= 1){
        for (int i = tid; i < NB1; i += 256)
            B[i] = A[i] + ((i + off < NB1) ? A[i + off] : 0);
        __syncthreads();
        int* t = A; A = B; B = t;
    }
    for (int i = tid; i < NB1; i += 256)
        if (A[i] >= TOPK && (i == NB1-1 || A[i+1] < TOPK)) sB1 = i;
    __syncthreads();
    const int b1 = sB1;

    int cnt = CCNT(b); if (cnt > BCAP) cnt = BCAP;
    const unsigned long long* src = g_cand[b];
    unsigned long long* sv = g_surv[b];
    const int lane = tid & 31;
    const unsigned lmask = (1u << lane) - 1u;
    const int start = blockIdx.x*256 + tid;
    const int step  = gridDim.x*256;
    for (int i = start; i < cnt; i += step){
        unsigned long long kk = src[i];
        float v = __uint_as_float((unsigned)(kk >> 32));
        bool take = bin1f(v) >= b1;
        unsigned bal = __ballot_sync(0xffffffffu, take);
        int wb = 0;
        if (lane == 0 && bal) wb = atomicAdd(&SCNT(b), __popc(bal));
        wb = __shfl_sync(0xffffffffu, wb, 0);
        if (take){
            int pos = wb + __popc(bal & lmask);
            if (pos < SCAP) sv[pos] = kk;
        }
    }
}

// K3: exact top-100 by O(m^2) pairwise ranking (no sort, no barriers in the
// rank loop), then gather offset/wh and decode. grid = BN, 1024 threads.
__global__ __launch_bounds__(1024) void rank_kernel(const float* __restrict__ offset,
                                                    const float* __restrict__ wh,
                                                    float* __restrict__ out){
    __shared__ unsigned long long sv[SCAP];
    const int b   = blockIdx.x;
    const int tid = threadIdx.x;
    int m = SCNT(b); if (m > SCAP) m = SCAP;

    for (int i = tid; i < m; i += 1024) sv[i] = g_surv[b][i];
    __syncthreads();

    #pragma unroll
    for (int t = 0; t < 2; ++t){
        int e = tid + t*1024;
        if (e < m){
            unsigned long long key = sv[e];
            int rank = 0;
            for (int j = 0; j < m; ++j) rank += (sv[j] > key);
            if (rank < TOPK){
                unsigned vb = (unsigned)(key >> 32);
                int idx = (int)(~(unsigned)key);
                float score = __uint_as_float(vb);
                int chn = idx / HWN;
                int spatial = idx - chn*HWN;
                int ys = spatial >> 7, xs = spatial & (WN-1);
                const float* offb = offset + (size_t)b * 2 * HWN;
                const float* whb  = wh     + (size_t)b * 2 * HWN;
                float ox = offb[spatial], oy = offb[HWN + spatial];
                float ww = whb[spatial],  hh = whb[HWN + spatial];
                float cx = (float)xs + ox, cy = (float)ys + oy;
                float hw2 = ww * 0.5f, hh2 = hh * 0.5f;

                float* out_ids = out;                 // (B,100,1)
                float* out_sc  = out + BN*TOPK;       // (B,100,1)
                float* out_bb  = out + 2*BN*TOPK;     // (B,100,4)
                out_ids[b*TOPK + rank] = (float)chn;
                out_sc [b*TOPK + rank] = score;
                float* bbp = out_bb + (size_t)(b*TOPK + rank)*4;
                bbp[0] = (cx - hw2)*4.0f;
                bbp[1] = (cy - hh2)*4.0f;
                bbp[2] = (cx + hw2)*4.0f;
                bbp[3] = (cy + hh2)*4.0f;
            }
        }
    }
}

extern "C" void kernel_launch(void* const* d_in, const int* in_sizes, int n_in,
                              void* d_out, int out_size){
    const float* hm     = (const float*)d_in[0];
    const float* offset = (const float*)d_in[1];
    const float* wh     = (const float*)d_in[2];
    float* out = (float*)d_out;

    void* zptr = nullptr;
    cudaGetSymbolAddress(&zptr, g_zeroed);
    cudaMemsetAsync(zptr, 0, sizeof(int)*(BN*NB1 + 2*BN));

    nms_kernel<<<NPLANES*4, 256>>>(hm);
    filter_kernel<<<dim3(8, BN), 256>>>();
    rank_kernel<<<BN, 1024>>>(offset, wh, out);
}

// round 4
// speedup vs baseline: 3.6818x; 3.6818x over previous
#include <cuda_runtime.h>

#define BN   16
#define CN   80
#define HN   128
#define WN   128
#define HWN  (HN*WN)
#define NPLANES (BN*CN)
#define TOPK 100
#define NB1  2048
#define CHUNK 32                    // rows per nms block
#define NCHUNK (HN/CHUNK)           // 4
#define NBLK (NPLANES*NCHUNK)       // 5120
#define PCCAP (CHUNK*WN)            // 4096: hard upper bound on maxima per chunk
#define SCAP 2048                   // per-batch survivor cap (expected ~640)

// ---- scratch (device globals; allocation-free contract) ----
__device__ unsigned long long g_cand2[NBLK][PCCAP]; // per-chunk slices
__device__ int g_pcnt[NBLK];                        // per-chunk counts (written unconditionally)
__device__ unsigned long long g_surv[BN][SCAP];
// zeroed each call via one memset: [BN*NB1 hist | BN scnt]
__device__ int g_zeroed[BN*NB1 + BN];
#define HIST(b,i) g_zeroed[(b)*NB1 + (i)]
#define SCNT(b)   g_zeroed[BN*NB1 + (b)]

__device__ __forceinline__ int bin1f(float v){
    int b = (int)(v * 2048.0f);
    return b < 0 ? 0 : (b > NB1-1 ? NB1-1 : b);
}

// K1: 3x3 NMS. One block per 32-row chunk (5120 blocks). Private output slice,
// shared counter + shared histogram -> zero contended global atomics.
__global__ __launch_bounds__(256) void nms_kernel(const float* __restrict__ hm){
    __shared__ float sp[(CHUNK+2)*WN];
    __shared__ int shist[NB1];
    __shared__ int scnt;
    const int blk   = blockIdx.x;
    const int plane = blk >> 2;
    const int chunk = blk & 3;
    const int b  = plane / CN;
    const int ch = plane % CN;
    const int r0 = chunk * CHUNK;
    const float* base = hm + (size_t)plane * HWN;

    if (threadIdx.x == 0) scnt = 0;
    for (int i = threadIdx.x; i < NB1; i += 256) shist[i] = 0;

    // load 34 rows (edge-guarded), float4
    for (int i = threadIdx.x; i < (CHUNK+2)*(WN/4); i += 256){
        int row = i >> 5;
        int q   = i & 31;
        int g   = r0 - 1 + row;
        if (g >= 0 && g < HN)
            ((float4*)sp)[row*(WN/4) + q] = ((const float4*)(base + (size_t)g*WN))[q];
    }
    __syncthreads();

    const int lane = threadIdx.x & 31;
    const unsigned lmask = (1u << lane) - 1u;
    unsigned long long* dst = g_cand2[blk];

    #pragma unroll 1
    for (int it = 0; it < (CHUNK*WN)/256; ++it){
        int pix = it*256 + threadIdx.x;
        int row = pix >> 7;
        int x   = pix & (WN-1);
        int y   = r0 + row;
        const float* cur = sp + (row+1)*WN;
        float v = cur[x];
        bool keep = true;
        bool hasL = x > 0, hasR = x < WN-1, hasU = y > 0, hasD = y < HN-1;
        if (hasU){
            const float* r = cur - WN;
            if (hasL && v < r[x-1]) keep = false;
            if (v < r[x])           keep = false;
            if (hasR && v < r[x+1]) keep = false;
        }
        if (hasL && v < cur[x-1]) keep = false;
        if (hasR && v < cur[x+1]) keep = false;
        if (hasD){
            const float* r = cur + WN;
            if (hasL && v < r[x-1]) keep = false;
            if (v < r[x])           keep = false;
            if (hasR && v < r[x+1]) keep = false;
        }

        if (keep) atomicAdd(&shist[bin1f(v)], 1);

        unsigned bal = __ballot_sync(0xffffffffu, keep);
        int wb = 0;
        if (lane == 0 && bal) wb = atomicAdd(&scnt, __popc(bal));
        wb = __shfl_sync(0xffffffffu, wb, 0);
        if (keep){
            int pos = wb + __popc(bal & lmask);
            unsigned vb  = __float_as_uint(v);
            unsigned idx = (unsigned)(ch*HWN + y*WN + x);
            dst[pos] = ((unsigned long long)vb << 32) | (unsigned)(~idx);
        }
    }
    __syncthreads();
    if (threadIdx.x == 0) g_pcnt[blk] = scnt;
    // flush nonzero hist bins (REDG, no return, scattered addresses)
    for (int i = threadIdx.x; i < NB1; i += 256){
        int c = shist[i];
        if (c) atomicAdd(&HIST(b, i), c);
    }
}

// K2: per-batch threshold via suffix scan of histogram, then compact survivors
// from the 320 chunk slices of this batch. grid=(20, BN), 256 threads.
__global__ __launch_bounds__(256) void filter_kernel(){
    __shared__ int s0[NB1], s1[NB1];
    __shared__ int sB1;
    const int b   = blockIdx.y;
    const int tid = threadIdx.x;

    for (int i = tid; i < NB1; i += 256) s0[i] = HIST(b, i);
    __syncthreads();
    int* A = s0; int* B = s1;
    for (int off = 1; off < NB1; off <<= 1){
        for (int i = tid; i < NB1; i += 256)
            B[i] = A[i] + ((i + off < NB1) ? A[i + off] : 0);
        __syncthreads();
        int* t = A; A = B; B = t;
    }
    for (int i = tid; i < NB1; i += 256)
        if (A[i] >= TOPK && (i == NB1-1 || A[i+1] < TOPK)) sB1 = i;
    __syncthreads();
    const int b1 = sB1;

    const int lane = tid & 31;
    const unsigned lmask = (1u << lane) - 1u;
    unsigned long long* sv = g_surv[b];
    const int blk0 = b * CN * NCHUNK;   // 320 consecutive chunk slices

    // each block handles chunk slices blockIdx.x, blockIdx.x+20, ...
    for (int s = blockIdx.x; s < CN*NCHUNK; s += 20){
        const int blk = blk0 + s;
        const int cnt = g_pcnt[blk];
        const unsigned long long* src = g_cand2[blk];
        for (int i = tid; i < cnt; i += 256){
            unsigned long long kk = src[i];
            float v = __uint_as_float((unsigned)(kk >> 32));
            bool take = bin1f(v) >= b1;
            unsigned bal = __ballot_sync(0xffffffffu, take);
            int wb = 0;
            if (lane == 0 && bal) wb = atomicAdd(&SCNT(b), __popc(bal));
            wb = __shfl_sync(0xffffffffu, wb, 0);
            if (take){
                int pos = wb + __popc(bal & lmask);
                if (pos < SCAP) sv[pos] = kk;
            }
        }
    }
}

// K3: exact top-100 by O(m^2) pairwise ranking, then decode. grid=BN, 1024 thr.
__global__ __launch_bounds__(1024) void rank_kernel(const float* __restrict__ offset,
                                                    const float* __restrict__ wh,
                                                    float* __restrict__ out){
    __shared__ unsigned long long sv[SCAP];
    const int b   = blockIdx.x;
    const int tid = threadIdx.x;
    int m = SCNT(b); if (m > SCAP) m = SCAP;

    for (int i = tid; i < m; i += 1024) sv[i] = g_surv[b][i];
    __syncthreads();

    #pragma unroll
    for (int t = 0; t < 2; ++t){
        int e = tid + t*1024;
        if (e < m){
            unsigned long long key = sv[e];
            int rank = 0;
            for (int j = 0; j < m; ++j) rank += (sv[j] > key);
            if (rank < TOPK){
                unsigned vb = (unsigned)(key >> 32);
                int idx = (int)(~(unsigned)key);
                float score = __uint_as_float(vb);
                int chn = idx / HWN;
                int spatial = idx - chn*HWN;
                int ys = spatial >> 7, xs = spatial & (WN-1);
                const float* offb = offset + (size_t)b * 2 * HWN;
                const float* whb  = wh     + (size_t)b * 2 * HWN;
                float ox = offb[spatial], oy = offb[HWN + spatial];
                float ww = whb[spatial],  hh = whb[HWN + spatial];
                float cx = (float)xs + ox, cy = (float)ys + oy;
                float hw2 = ww * 0.5f, hh2 = hh * 0.5f;

                float* out_ids = out;                 // (B,100,1)
                float* out_sc  = out + BN*TOPK;       // (B,100,1)
                float* out_bb  = out + 2*BN*TOPK;     // (B,100,4)
                out_ids[b*TOPK + rank] = (float)chn;
                out_sc [b*TOPK + rank] = score;
                float* bbp = out_bb + (size_t)(b*TOPK + rank)*4;
                bbp[0] = (cx - hw2)*4.0f;
                bbp[1] = (cy - hh2)*4.0f;
                bbp[2] = (cx + hw2)*4.0f;
                bbp[3] = (cy + hh2)*4.0f;
            }
        }
    }
}

extern "C" void kernel_launch(void* const* d_in, const int* in_sizes, int n_in,
                              void* d_out, int out_size){
    const float* hm     = (const float*)d_in[0];
    const float* offset = (const float*)d_in[1];
    const float* wh     = (const float*)d_in[2];
    float* out = (float*)d_out;

    void* zptr = nullptr;
    cudaGetSymbolAddress(&zptr, g_zeroed);
    cudaMemsetAsync(zptr, 0, sizeof(int)*(BN*NB1 + BN));

    nms_kernel<<<NBLK, 256>>>(hm);
    filter_kernel<<<dim3(20, BN), 256>>>();
    rank_kernel<<<BN, 1024>>>(offset, wh, out);
}

// round 5
// speedup vs baseline: 6.1679x; 1.6752x over previous
#include <cuda_runtime.h>

#define BN   16
#define CN   80
#define HN   128
#define WN   128
#define HWN  (HN*WN)
#define NPLANES (BN*CN)
#define TOPK 100
#define NB1  2048
#define PCAP 4096                   // per-plane candidate cap (expected ~1820)
#define SCAP 2048                   // per-batch survivor cap (expected ~640)
#define NEG_INF __int_as_float(0xff800000)

// ---- scratch (device globals; allocation-free contract) ----
__device__ unsigned long long g_cand[NPLANES][PCAP];  // packed (valbits<<32)|~idx
__device__ int g_pcnt[NPLANES];
__device__ unsigned long long g_surv[BN][SCAP];
// zeroed each call via one memset: [BN*NB1 hist | BN scnt]
__device__ int g_zeroed[BN*NB1 + BN];
#define HIST(b,i) g_zeroed[(b)*NB1 + (i)]
#define SCNT(b)   g_zeroed[BN*NB1 + (b)]

__device__ __forceinline__ int bin1f(float v){
    int b = (int)(v * 2048.0f);
    return b < 0 ? 0 : (b > NB1-1 ? NB1-1 : b);
}

// Horizontal 3-max of a row held as float4-per-lane (32 lanes cover 128 cols).
__device__ __forceinline__ float4 hmax4(float4 v, int lane){
    float left  = __shfl_up_sync(0xffffffffu, v.w, 1);
    float right = __shfl_down_sync(0xffffffffu, v.x, 1);
    if (lane == 0)  left  = NEG_INF;
    if (lane == 31) right = NEG_INF;
    float4 h;
    h.x = fmaxf(fmaxf(left, v.x), v.y);
    h.y = fmaxf(fmaxf(v.x, v.y), v.z);
    h.z = fmaxf(fmaxf(v.y, v.z), v.w);
    h.w = fmaxf(fmaxf(v.z, v.w), right);
    return h;
}

// K1: 3x3 NMS, register-rolling separable max. One block per plane (1280).
// 8 warps x 16 rows; lane owns 4 columns; no plane staging in shared.
__global__ __launch_bounds__(256) void nms_kernel(const float* __restrict__ hm){
    __shared__ int shist[NB1];
    __shared__ int scnt;
    const int plane = blockIdx.x;
    const int b  = plane / CN;
    const int ch = plane % CN;
    const int wid  = threadIdx.x >> 5;
    const int lane = threadIdx.x & 31;
    const int r0 = wid * 16;
    const float* base = hm + (size_t)plane * HWN + lane*4;

    if (threadIdx.x == 0) scnt = 0;
    for (int i = threadIdx.x; i < NB1; i += 256) shist[i] = 0;
    __syncthreads();

    unsigned long long* dst = g_cand[plane];

    float4 v_cur, v_next, h_prev, h_cur, h_next;
    if (r0 > 0){
        float4 vm = *(const float4*)(base + (size_t)(r0-1)*WN);
        h_prev = hmax4(vm, lane);
    } else {
        h_prev = make_float4(NEG_INF, NEG_INF, NEG_INF, NEG_INF);
    }
    v_cur = *(const float4*)(base + (size_t)r0*WN);
    h_cur = hmax4(v_cur, lane);

    #pragma unroll 1
    for (int r = r0; r < r0 + 16; ++r){
        if (r + 1 < HN){
            v_next = *(const float4*)(base + (size_t)(r+1)*WN);
            h_next = hmax4(v_next, lane);
        } else {
            h_next = make_float4(NEG_INF, NEG_INF, NEG_INF, NEG_INF);
        }
        float wm0 = fmaxf(fmaxf(h_prev.x, h_cur.x), h_next.x);
        float wm1 = fmaxf(fmaxf(h_prev.y, h_cur.y), h_next.y);
        float wm2 = fmaxf(fmaxf(h_prev.z, h_cur.z), h_next.z);
        float wm3 = fmaxf(fmaxf(h_prev.w, h_cur.w), h_next.w);
        float vv0 = v_cur.x, vv1 = v_cur.y, vv2 = v_cur.z, vv3 = v_cur.w;

        #pragma unroll
        for (int e = 0; e < 4; ++e){
            float v  = (e==0)?vv0:(e==1)?vv1:(e==2)?vv2:vv3;
            float wm = (e==0)?wm0:(e==1)?wm1:(e==2)?wm2:wm3;
            if (v == wm){
                int pos = atomicAdd(&scnt, 1);
                if (pos < PCAP){
                    unsigned vb  = __float_as_uint(v);
                    unsigned idx = (unsigned)(ch*HWN + r*WN + lane*4 + e);
                    dst[pos] = ((unsigned long long)vb << 32) | (unsigned)(~idx);
                }
                atomicAdd(&shist[bin1f(v)], 1);
            }
        }
        h_prev = h_cur; h_cur = h_next; v_cur = v_next;
    }
    __syncthreads();
    if (threadIdx.x == 0) g_pcnt[plane] = (scnt > PCAP) ? PCAP : scnt;
    for (int i = threadIdx.x; i < NB1; i += 256){
        int c = shist[i];
        if (c) atomicAdd(&HIST(b, i), c);
    }
}

// K2: per-batch threshold via suffix scan of histogram, then compact survivors
// from the 80 plane slices of this batch. grid=(20, BN), 256 threads.
__global__ __launch_bounds__(256) void filter_kernel(){
    __shared__ int s0[NB1], s1[NB1];
    __shared__ int sB1;
    const int b   = blockIdx.y;
    const int tid = threadIdx.x;

    for (int i = tid; i < NB1; i += 256) s0[i] = HIST(b, i);
    __syncthreads();
    int* A = s0; int* B = s1;
    for (int off = 1; off < NB1; off <<= 1){
        for (int i = tid; i < NB1; i += 256)
            B[i] = A[i] + ((i + off < NB1) ? A[i + off] : 0);
        __syncthreads();
        int* t = A; A = B; B = t;
    }
    for (int i = tid; i < NB1; i += 256)
        if (A[i] >= TOPK && (i == NB1-1 || A[i+1] < TOPK)) sB1 = i;
    __syncthreads();
    const int b1 = sB1;

    const int lane = tid & 31;
    const unsigned lmask = (1u << lane) - 1u;
    unsigned long long* sv = g_surv[b];

    for (int p = blockIdx.x; p < CN; p += 20){
        const int plane = b*CN + p;
        const int cnt = g_pcnt[plane];
        const unsigned long long* src = g_cand[plane];
        for (int i = tid; i < cnt; i += 256){
            unsigned long long kk = src[i];
            float v = __uint_as_float((unsigned)(kk >> 32));
            bool take = bin1f(v) >= b1;
            unsigned bal = __ballot_sync(0xffffffffu, take);
            int wb = 0;
            if (lane == 0 && bal) wb = atomicAdd(&SCNT(b), __popc(bal));
            wb = __shfl_sync(0xffffffffu, wb, 0);
            if (take){
                int pos = wb + __popc(bal & lmask);
                if (pos < SCAP) sv[pos] = kk;
            }
        }
    }
}

// K3: exact top-100 by O(m^2) pairwise ranking, then decode. grid=BN, 1024 thr.
__global__ __launch_bounds__(1024) void rank_kernel(const float* __restrict__ offset,
                                                    const float* __restrict__ wh,
                                                    float* __restrict__ out){
    __shared__ unsigned long long sv[SCAP];
    const int b   = blockIdx.x;
    const int tid = threadIdx.x;
    int m = SCNT(b); if (m > SCAP) m = SCAP;

    for (int i = tid; i < m; i += 1024) sv[i] = g_surv[b][i];
    __syncthreads();

    #pragma unroll
    for (int t = 0; t < 2; ++t){
        int e = tid + t*1024;
        if (e < m){
            unsigned long long key = sv[e];
            int rank = 0;
            for (int j = 0; j < m; ++j) rank += (sv[j] > key);
            if (rank < TOPK){
                unsigned vb = (unsigned)(key >> 32);
                int idx = (int)(~(unsigned)key);
                float score = __uint_as_float(vb);
                int chn = idx / HWN;
                int spatial = idx - chn*HWN;
                int ys = spatial >> 7, xs = spatial & (WN-1);
                const float* offb = offset + (size_t)b * 2 * HWN;
                const float* whb  = wh     + (size_t)b * 2 * HWN;
                float ox = offb[spatial], oy = offb[HWN + spatial];
                float ww = whb[spatial],  hh = whb[HWN + spatial];
                float cx = (float)xs + ox, cy = (float)ys + oy;
                float hw2 = ww * 0.5f, hh2 = hh * 0.5f;

                float* out_ids = out;                 // (B,100,1)
                float* out_sc  = out + BN*TOPK;       // (B,100,1)
                float* out_bb  = out + 2*BN*TOPK;     // (B,100,4)
                out_ids[b*TOPK + rank] = (float)chn;
                out_sc [b*TOPK + rank] = score;
                float* bbp = out_bb + (size_t)(b*TOPK + rank)*4;
                bbp[0] = (cx - hw2)*4.0f;
                bbp[1] = (cy - hh2)*4.0f;
                bbp[2] = (cx + hw2)*4.0f;
                bbp[3] = (cy + hh2)*4.0f;
            }
        }
    }
}

extern "C" void kernel_launch(void* const* d_in, const int* in_sizes, int n_in,
                              void* d_out, int out_size){
    const float* hm     = (const float*)d_in[0];
    const float* offset = (const float*)d_in[1];
    const float* wh     = (const float*)d_in[2];
    float* out = (float*)d_out;

    void* zptr = nullptr;
    cudaGetSymbolAddress(&zptr, g_zeroed);
    cudaMemsetAsync(zptr, 0, sizeof(int)*(BN*NB1 + BN));

    nms_kernel<<<NPLANES, 256>>>(hm);
    filter_kernel<<<dim3(20, BN), 256>>>();
    rank_kernel<<<BN, 1024>>>(offset, wh, out);
}